// round 5
// baseline (speedup 1.0000x reference)
#include <cuda_runtime.h>
#include <cuda_bf16.h>
#include <cstdint>

// ---------------- problem constants ----------------
#define BB   8
#define NN   2048
#define DIN  2
#define DS   32
#define DO   32
#define GE   8
#define HID  32
#define DCAT 66
#define DGI  74
#define DBASIS 396
#define GOUT 96

#define TOTN (BB*NN)
#define SZ66 ((size_t)TOTN*DCAT)
#define SZ32 ((size_t)TOTN*DO)

#define NJ 9                 // n8 blocks (72 cols, 66 used)
#define NKS 128              // k16 blocks
#define PACK_ELEMS (BB*NJ*NKS*32)   // uint4 count = 294912

__device__ float g_scratch[6*1081344 + 2*524288];
__device__ uint4 g_packA[PACK_ELEMS];   // X / C
__device__ uint4 g_packB[PACK_ELEMS];   // T0 / T2 (reused)

#define OFF_X  ((size_t)0)
#define OFF_C  (SZ66)
#define OFF_T0 (2*SZ66)
#define OFF_T1 (3*SZ66)
#define OFF_T2 (4*SZ66)
#define OFF_T3 (5*SZ66)
#define OFF_ST (6*SZ66)
#define OFF_R  (6*SZ66 + SZ32)

__device__ __forceinline__ float sigmoidf_(float x) {
    return 1.0f / (1.0f + __expf(-x));
}

__device__ __forceinline__ void mma_bf16(float c[4], const uint32_t a[4], const uint32_t b[2]) {
    asm volatile(
        "mma.sync.aligned.m16n8k16.row.col.f32.bf16.bf16.f32 "
        "{%0,%1,%2,%3},{%4,%5,%6,%7},{%8,%9},{%0,%1,%2,%3};"
        : "+f"(c[0]), "+f"(c[1]), "+f"(c[2]), "+f"(c[3])
        : "r"(a[0]), "r"(a[1]), "r"(a[2]), "r"(a[3]), "r"(b[0]), "r"(b[1]));
}

// split float2 -> bf16x2 high + bf16x2 low-residual
__device__ __forceinline__ void split2(float2 v, uint32_t& h, uint32_t& l) {
    __nv_bfloat162 hh = __float22bfloat162_rn(v);
    h = *(uint32_t*)&hh;
    float2 r;
    r.x = v.x - __low2float(hh);
    r.y = v.y - __high2float(hh);
    __nv_bfloat162 ll = __float22bfloat162_rn(r);
    l = *(uint32_t*)&ll;
}

// ---------------------------------------------------------------------------
// Kernel 1: prep
// ---------------------------------------------------------------------------
__global__ void prep_kernel(const float* __restrict__ xt,
                            const float* __restrict__ s1,
                            const float* __restrict__ s2,
                            const float* __restrict__ ge,
                            const float* __restrict__ mlp_w,
                            const float* __restrict__ mlp_b,
                            float* __restrict__ gX,
                            float* __restrict__ gstate)
{
    __shared__ float sg[8][DGI];
    const int t  = threadIdx.x;
    const int nb = blockIdx.x * 8;

    for (int idx = t; idx < 8 * DGI; idx += 256) {
        int nn = idx / DGI, i = idx % DGI;
        int node = nb + nn;
        float v;
        if (i < DIN)            v = xt[node*DIN + i];
        else if (i < DIN+DS)    v = s1[node*DS + (i-DIN)];
        else if (i < DIN+2*DS)  v = s2[node*DS + (i-DIN-DS)];
        else                    v = ge[node*GE + (i-DIN-2*DS)];
        sg[nn][i] = v;
    }
    __syncthreads();

    for (int idx = t; idx < 8 * DCAT; idx += 256) {
        int nn = idx / DCAT, i = idx % DCAT;
        gX[(size_t)(nb+nn)*DCAT + i] = sg[nn][i];
    }

    const int n = t >> 5;
    const int c = t & 31;
    float acc = mlp_b[c];
#pragma unroll 8
    for (int i = 0; i < DGI; i++)
        acc = fmaf(sg[n][i], mlp_w[i*DO + c], acc);
    float mr = sigmoidf_(acc);

    int node = nb + n;
    float a = s1[node*DS + c];
    float b = s2[node*DS + c];
    gstate[node*DS + c] = mr*a + (1.0f - mr)*b;
}

// ---------------------------------------------------------------------------
// Pack kernel: fp32 [16384][66] -> fragment-native h/l layout
// dst[((b*9 + j)*128 + kb)*32 + lane] = {h(k0),h(k1),h(k8),h(k9),l(...)} for
// col n = j*8 + lane/4, k-base = kb*16 + 2*(lane%4). grid (128,8), 288 thr.
// ---------------------------------------------------------------------------
__global__ __launch_bounds__(288) void pack_kernel(const float* __restrict__ src,
                                                   uint4* __restrict__ dst)
{
    __shared__ float tile[16][68];
    const int t  = threadIdx.x;
    const int kb = blockIdx.x;
    const int b  = blockIdx.y;
    const int node0 = b*NN + kb*16;

    for (int idx = t; idx < 16*DCAT; idx += 288) {
        int r = idx / DCAT, c = idx - r*DCAT;
        tile[r][c] = src[(size_t)(node0 + r)*DCAT + c];
    }
    __syncthreads();

    const int j    = t >> 5;
    const int lane = t & 31;
    const int g    = lane >> 2;
    const int tg   = lane & 3;
    const int n    = j*8 + g;

    float v0 = 0.f, v1 = 0.f, v2 = 0.f, v3 = 0.f;
    if (n < DCAT) {
        v0 = tile[2*tg    ][n];
        v1 = tile[2*tg + 1][n];
        v2 = tile[2*tg + 8][n];
        v3 = tile[2*tg + 9][n];
    }
    uint32_t h01, l01, h89, l89;
    split2(make_float2(v0, v1), h01, l01);
    split2(make_float2(v2, v3), h89, l89);

    uint4 o; o.x = h01; o.y = h89; o.z = l01; o.w = l89;
    dst[((size_t)(b*NJ + j)*NKS + kb)*32 + lane] = o;
}

// ---------------------------------------------------------------------------
// Kernel 2: smem-free tensor-core GEMM (A direct-LDG frags, packed B)
// CTA: 64 thr = 2 warps x 32 rows; tile M=64, N=72(66). grid (32, 8).
// ---------------------------------------------------------------------------
__global__ __launch_bounds__(64) void gemm_tc(const float* __restrict__ A,
                                              const uint4* __restrict__ Bp,
                                              const float* __restrict__ Base,
                                              float* __restrict__ Out,
                                              float alpha, float beta)
{
    const int t    = threadIdx.x;
    const int w    = t >> 5;
    const int lane = t & 31;
    const int g    = lane >> 2;
    const int tg   = lane & 3;
    const int b    = blockIdx.y;
    const int row0 = blockIdx.x * 64 + w * 32;

    const float* Ab = A + ((size_t)b * NN + row0) * NN;
    const uint4* Bb = Bp + (size_t)b * NJ * NKS * 32 + lane;

    float acc[2][NJ][4];
#pragma unroll
    for (int mi = 0; mi < 2; mi++)
#pragma unroll
        for (int j = 0; j < NJ; j++)
#pragma unroll
            for (int q = 0; q < 4; q++) acc[mi][j][q] = 0.0f;

    float2 ar[2][8];
    uint4  br[2][NJ];

    auto LD = [&](int ks, int p) {
        const int k = ks*16 + 2*tg;
#pragma unroll
        for (int mi = 0; mi < 2; mi++) {
            const float* ap = Ab + (size_t)(mi*16 + g)*NN + k;
            ar[p][mi*4+0] = *(const float2*)(ap);
            ar[p][mi*4+1] = *(const float2*)(ap + 8*NN);
            ar[p][mi*4+2] = *(const float2*)(ap + 8);
            ar[p][mi*4+3] = *(const float2*)(ap + 8*NN + 8);
        }
#pragma unroll
        for (int j = 0; j < NJ; j++)
            br[p][j] = Bb[((size_t)j*NKS + ks)*32];
    };

    LD(0, 0);

    for (int ks = 0; ks < NKS; ks++) {
        const int p = ks & 1;
        if (ks < NKS-1) LD(ks+1, p ^ 1);

        uint32_t ah[2][4], al[2][4];
#pragma unroll
        for (int mi = 0; mi < 2; mi++)
#pragma unroll
            for (int q = 0; q < 4; q++)
                split2(ar[p][mi*4+q], ah[mi][q], al[mi][q]);

#pragma unroll
        for (int j = 0; j < NJ; j++) {
            uint32_t bh[2], bl[2];
            bh[0] = br[p][j].x; bh[1] = br[p][j].y;
            bl[0] = br[p][j].z; bl[1] = br[p][j].w;
#pragma unroll
            for (int mi = 0; mi < 2; mi++) {
                mma_bf16(acc[mi][j], ah[mi], bh);
                mma_bf16(acc[mi][j], al[mi], bh);
                mma_bf16(acc[mi][j], ah[mi], bl);
            }
        }
    }

#pragma unroll
    for (int mi = 0; mi < 2; mi++) {
#pragma unroll
        for (int j = 0; j < NJ; j++) {
            int col = j*8 + 2*tg;
            if (col < DCAT) {
#pragma unroll
                for (int h2 = 0; h2 < 2; h2++) {
                    int row = row0 + mi*16 + g + h2*8;
                    size_t o = ((size_t)b * NN + row) * DCAT + col;
                    float2 v;
                    v.x = alpha * acc[mi][j][h2*2 + 0];
                    v.y = alpha * acc[mi][j][h2*2 + 1];
                    if (Base) {
                        float2 bs = *(const float2*)(Base + o);
                        v.x = fmaf(beta, bs.x, v.x);
                        v.y = fmaf(beta, bs.y, v.y);
                    }
                    *(float2*)(Out + o) = v;
                }
            }
        }
    }
}

// ---------------------------------------------------------------------------
// Kernel 3: gate combine — 16 nodes/block, 384 thr
// ---------------------------------------------------------------------------
__global__ __launch_bounds__(384) void combine_gate(
                             const float* __restrict__ X,
                             const float* __restrict__ T0,
                             const float* __restrict__ T1,
                             const float* __restrict__ T2,
                             const float* __restrict__ T3,
                             const float* __restrict__ gate_w,
                             const float* __restrict__ gate_b,
                             const float* __restrict__ xt,
                             const float* __restrict__ s1,
                             const float* __restrict__ s2,
                             float* __restrict__ cand,
                             float* __restrict__ r_out)
{
    __shared__ float s[16][DBASIS];
    const int t  = threadIdx.x;
    const int nb = blockIdx.x * 16;

    for (int idx = t; idx < 16*DBASIS; idx += 384) {
        int n = idx / DBASIS, i = idx - n*DBASIS;
        int term = i / DCAT, w = i - term*DCAT;
        const float* src;
        switch (term) {
            case 0: src = X;  break;
            case 1: src = T0; break;
            case 2: src = T1; break;
            case 3: src = X;  break;
            case 4: src = T2; break;
            default: src = T3; break;
        }
        s[n][i] = src[(size_t)(nb+n)*DCAT + w];
    }
    __syncthreads();

    const int c = t % 96;
    const int g = t / 96;
    float acc[4];
    float bc = gate_b[c];
#pragma unroll
    for (int q = 0; q < 4; q++) acc[q] = bc;

    for (int i = 0; i < DBASIS; i++) {
        float w = __ldg(&gate_w[i*GOUT + c]);
#pragma unroll
        for (int q = 0; q < 4; q++)
            acc[q] = fmaf(s[g*4 + q][i], w, acc[q]);
    }

#pragma unroll
    for (int q = 0; q < 4; q++) {
        int node = nb + g*4 + q;
        float v = sigmoidf_(acc[q]);
        if (c < DO) {
            cand[(size_t)node*DCAT + DIN + c] = v * s1[node*DS + c];
        } else if (c < 2*DO) {
            int cc = c - DO;
            cand[(size_t)node*DCAT + DIN + DS + cc] = v * s2[node*DS + cc];
        } else {
            r_out[node*DO + (c - 2*DO)] = v;
        }
        if (c < DIN)
            cand[(size_t)node*DCAT + c] = xt[node*DIN + c];
    }
}

// ---------------------------------------------------------------------------
// Kernel 4: final — 16 nodes/block, 512 thr
// ---------------------------------------------------------------------------
__global__ __launch_bounds__(512) void final_kernel(
                             const float* __restrict__ C,
                             const float* __restrict__ T0,
                             const float* __restrict__ T1,
                             const float* __restrict__ T2,
                             const float* __restrict__ T3,
                             const float* __restrict__ upd_w,
                             const float* __restrict__ upd_b,
                             const float* __restrict__ hop_w,
                             const float* __restrict__ hop_b,
                             const float* __restrict__ g_r,
                             const float* __restrict__ g_state,
                             float* __restrict__ out)
{
    __shared__ float s[16][DBASIS];
    __shared__ float hsh[16][DO];
    const int t  = threadIdx.x;
    const int nb = blockIdx.x * 16;

    for (int idx = t; idx < 16*DBASIS; idx += 512) {
        int n = idx / DBASIS, i = idx - n*DBASIS;
        int term = i / DCAT, w = i - term*DCAT;
        const float* src;
        switch (term) {
            case 0: src = C;  break;
            case 1: src = T0; break;
            case 2: src = T1; break;
            case 3: src = C;  break;
            case 4: src = T2; break;
            default: src = T3; break;
        }
        s[n][i] = src[(size_t)(nb+n)*DCAT + w];
    }
    __syncthreads();

    const int n = t >> 5;
    const int c = t & 31;
    const int node = nb + n;

    float acc = upd_b[c];
    for (int i = 0; i < DBASIS; i++)
        acc = fmaf(s[n][i], __ldg(&upd_w[i*DO + c]), acc);

    float hc = tanhf(acc);
    float r  = g_r[node*DO + c];
    float st = g_state[node*DS + c];
    float h  = r*st + (1.0f - r)*hc;

    out[(size_t)node*DO + c] = h;
    hsh[n][c] = h;
    __syncthreads();

    float a2 = hop_b[c];
#pragma unroll
    for (int i = 0; i < HID; i++)
        a2 = fmaf(hsh[n][i], hop_w[i*HID + c], a2);
    out[(size_t)TOTN*DO + (size_t)node*HID + c] = a2;
}

// ---------------------------------------------------------------------------
// launch
// ---------------------------------------------------------------------------
extern "C" void kernel_launch(void* const* d_in, const int* in_sizes, int n_in,
                              void* d_out, int out_size)
{
    const float* xt     = (const float*)d_in[0];
    const float* s1     = (const float*)d_in[1];
    const float* s2     = (const float*)d_in[2];
    const float* ge     = (const float*)d_in[3];
    const float* sup    = (const float*)d_in[4];
    const float* mlp_w  = (const float*)d_in[5];
    const float* mlp_b  = (const float*)d_in[6];
    const float* gate_w = (const float*)d_in[7];
    const float* gate_b = (const float*)d_in[8];
    const float* upd_w  = (const float*)d_in[9];
    const float* upd_b  = (const float*)d_in[10];
    const float* hop_w  = (const float*)d_in[11];
    const float* hop_b  = (const float*)d_in[12];
    float* out = (float*)d_out;

    float* scr = nullptr;
    cudaGetSymbolAddress((void**)&scr, g_scratch);
    uint4* pA = nullptr;
    cudaGetSymbolAddress((void**)&pA, g_packA);
    uint4* pB = nullptr;
    cudaGetSymbolAddress((void**)&pB, g_packB);

    float* gX  = scr + OFF_X;
    float* gC  = scr + OFF_C;
    float* gT0 = scr + OFF_T0;
    float* gT1 = scr + OFF_T1;
    float* gT2 = scr + OFF_T2;
    float* gT3 = scr + OFF_T3;
    float* gST = scr + OFF_ST;
    float* gR  = scr + OFF_R;

    const float* A0 = sup;
    const float* A1 = sup + (size_t)BB * NN * NN;

    dim3 ggrid(NN / 64, BB);
    dim3 pgrid(NKS, BB);

    prep_kernel<<<TOTN/8, 256>>>(xt, s1, s2, ge, mlp_w, mlp_b, gX, gST);
    pack_kernel<<<pgrid, 288>>>(gX, pA);

    gemm_tc<<<ggrid, 64>>>(A0, pA, nullptr, gT0, 1.0f,  0.0f);
    pack_kernel<<<pgrid, 288>>>(gT0, pB);
    gemm_tc<<<ggrid, 64>>>(A0, pB, gX,      gT1, 2.0f, -1.0f);
    gemm_tc<<<ggrid, 64>>>(A1, pA, nullptr, gT2, 1.0f,  0.0f);
    pack_kernel<<<pgrid, 288>>>(gT2, pB);
    gemm_tc<<<ggrid, 64>>>(A1, pB, gX,      gT3, 2.0f, -1.0f);

    combine_gate<<<TOTN/16, 384>>>(gX, gT0, gT1, gT2, gT3,
                                   gate_w, gate_b, xt, s1, s2, gC, gR);
    pack_kernel<<<pgrid, 288>>>(gC, pA);

    gemm_tc<<<ggrid, 64>>>(A0, pA, nullptr, gT0, 1.0f,  0.0f);
    pack_kernel<<<pgrid, 288>>>(gT0, pB);
    gemm_tc<<<ggrid, 64>>>(A0, pB, gC,      gT1, 2.0f, -1.0f);
    gemm_tc<<<ggrid, 64>>>(A1, pA, nullptr, gT2, 1.0f,  0.0f);
    pack_kernel<<<pgrid, 288>>>(gT2, pB);
    gemm_tc<<<ggrid, 64>>>(A1, pB, gC,      gT3, 2.0f, -1.0f);

    final_kernel<<<TOTN/16, 512>>>(gC, gT0, gT1, gT2, gT3,
                                   upd_w, upd_b, hop_w, hop_b,
                                   gR, gST, out);
}

// round 9
// speedup vs baseline: 1.4728x; 1.4728x over previous
#include <cuda_runtime.h>
#include <cuda_bf16.h>
#include <cstdint>

// ---------------- problem constants ----------------
#define BB   8
#define NN   2048
#define DIN  2
#define DS   32
#define DO   32
#define GE   8
#define HID  32
#define DCAT 66
#define DGI  74
#define DBASIS 396
#define GOUT 96

#define TOTN (BB*NN)
#define SZ66 ((size_t)TOTN*DCAT)
#define SZ32 ((size_t)TOTN*DO)

#define NJ 9                 // n8 blocks (72 cols, 66 used)
#define NKS 128              // k16 blocks
#define PACK_ELEMS ((size_t)BB*NJ*NKS*32)   // uint4 per pack image

__device__ float g_scratch[6*1081344 + 2*524288];
__device__ uint4 g_packA[PACK_ELEMS];       // packed X or C
__device__ uint4 g_packB[2*PACK_ELEMS];     // packed T0 (slot0) / T2 (slot1)

#define OFF_X  ((size_t)0)
#define OFF_C  (SZ66)
#define OFF_T0 (2*SZ66)
#define OFF_T1 (3*SZ66)
#define OFF_T2 (4*SZ66)
#define OFF_T3 (5*SZ66)
#define OFF_ST (6*SZ66)
#define OFF_R  (6*SZ66 + SZ32)

__device__ __forceinline__ float sigmoidf_(float x) {
    return 1.0f / (1.0f + __expf(-x));
}

__device__ __forceinline__ void mma_bf16(float c[4], const uint32_t a[4], const uint32_t b[2]) {
    asm volatile(
        "mma.sync.aligned.m16n8k16.row.col.f32.bf16.bf16.f32 "
        "{%0,%1,%2,%3},{%4,%5,%6,%7},{%8,%9},{%0,%1,%2,%3};"
        : "+f"(c[0]), "+f"(c[1]), "+f"(c[2]), "+f"(c[3])
        : "r"(a[0]), "r"(a[1]), "r"(a[2]), "r"(a[3]), "r"(b[0]), "r"(b[1]));
}

// split float2 -> bf16x2 high + bf16x2 low-residual
__device__ __forceinline__ void split2(float2 v, uint32_t& h, uint32_t& l) {
    __nv_bfloat162 hh = __float22bfloat162_rn(v);
    h = *(uint32_t*)&hh;
    float2 r;
    r.x = v.x - __low2float(hh);
    r.y = v.y - __high2float(hh);
    __nv_bfloat162 ll = __float22bfloat162_rn(r);
    l = *(uint32_t*)&ll;
}

// pack one 16-node x 66-col tile (smem) -> fragment-native h/l image.
// caller: 288 participating threads (t < 288), tile stride TS floats per row.
template<int TS>
__device__ __forceinline__ void pack_tile(const float (*tile)[TS], uint4* dst,
                                          int b, int kb, int t)
{
    const int j    = t >> 5;
    const int lane = t & 31;
    const int g    = lane >> 2;
    const int tg   = lane & 3;
    const int n    = j*8 + g;

    float v0 = 0.f, v1 = 0.f, v2 = 0.f, v3 = 0.f;
    if (n < DCAT) {
        v0 = tile[2*tg    ][n];
        v1 = tile[2*tg + 1][n];
        v2 = tile[2*tg + 8][n];
        v3 = tile[2*tg + 9][n];
    }
    uint32_t h01, l01, h89, l89;
    split2(make_float2(v0, v1), h01, l01);
    split2(make_float2(v2, v3), h89, l89);

    uint4 o; o.x = h01; o.y = h89; o.z = l01; o.w = l89;
    dst[((size_t)(b*NJ + j)*NKS + kb)*32 + lane] = o;
}

// ---------------------------------------------------------------------------
// Kernel 1: prep — gate MLP -> mr -> state; write X and packed X
// 16 nodes/block, 512 threads
// ---------------------------------------------------------------------------
__global__ __launch_bounds__(512) void prep_kernel(
                            const float* __restrict__ xt,
                            const float* __restrict__ s1,
                            const float* __restrict__ s2,
                            const float* __restrict__ ge,
                            const float* __restrict__ mlp_w,
                            const float* __restrict__ mlp_b,
                            float* __restrict__ gX,
                            float* __restrict__ gstate,
                            uint4* __restrict__ packX)
{
    __shared__ float sg[16][DGI];
    const int t  = threadIdx.x;
    const int nb = blockIdx.x * 16;

    for (int idx = t; idx < 16 * DGI; idx += 512) {
        int nn = idx / DGI, i = idx % DGI;
        int node = nb + nn;
        float v;
        if (i < DIN)            v = xt[node*DIN + i];
        else if (i < DIN+DS)    v = s1[node*DS + (i-DIN)];
        else if (i < DIN+2*DS)  v = s2[node*DS + (i-DIN-DS)];
        else                    v = ge[node*GE + (i-DIN-2*DS)];
        sg[nn][i] = v;
    }
    __syncthreads();

    // write X (first 66 cols)
    for (int idx = t; idx < 16 * DCAT; idx += 512) {
        int nn = idx / DCAT, i = idx % DCAT;
        gX[(size_t)(nb+nn)*DCAT + i] = sg[nn][i];
    }

    // gate MLP: 512 thr = 16 nodes x 32 channels
    const int n = t >> 5;
    const int c = t & 31;
    float acc = mlp_b[c];
#pragma unroll 8
    for (int i = 0; i < DGI; i++)
        acc = fmaf(sg[n][i], mlp_w[i*DO + c], acc);
    float mr = sigmoidf_(acc);

    int node = nb + n;
    float a = s1[node*DS + c];
    float b = s2[node*DS + c];
    gstate[node*DS + c] = mr*a + (1.0f - mr)*b;

    // fused pack of this 16-node tile (cols 0..65 of sg)
    if (t < 288) {
        const int bb = nb >> 11;            // batch
        const int kb = (nb & 2047) >> 4;    // k16 block within batch
        pack_tile<DGI>(sg, packX, bb, kb, t);
    }
}

// ---------------------------------------------------------------------------
// Pack kernel (for T0/T2 after GEMM): grid (128, 8, 2)
// ---------------------------------------------------------------------------
__global__ __launch_bounds__(288) void pack_kernel(const float* __restrict__ src,
                                                   size_t srcStride,
                                                   uint4* __restrict__ dst)
{
    __shared__ float tile[16][68];
    const int t  = threadIdx.x;
    const int kb = blockIdx.x;
    const int b  = blockIdx.y;
    const int z  = blockIdx.z;
    src += (size_t)z * srcStride;
    dst += (size_t)z * PACK_ELEMS;
    const int node0 = b*NN + kb*16;

    for (int idx = t; idx < 16*DCAT; idx += 288) {
        int r = idx / DCAT, c = idx - r*DCAT;
        tile[r][c] = src[(size_t)(node0 + r)*DCAT + c];
    }
    __syncthreads();
    pack_tile<68>(tile, dst, b, kb, t);
}

// ---------------------------------------------------------------------------
// Kernel 2: smem-free tensor-core GEMM, merged over supports (blockIdx.z)
// CTA: 128 thr = 4 warps x m16; tile M=64, N=72(66). grid (32, 8, 2).
// A fp32 direct-LDG fragments (in-reg bf16 split, 3-product); B packed.
// ---------------------------------------------------------------------------
__global__ __launch_bounds__(128) void gemm_tc(const float* __restrict__ A,
                                               const uint4* __restrict__ Bp,
                                               size_t bpStride,
                                               const float* __restrict__ Base,
                                               float* __restrict__ Out,
                                               float alpha, float beta)
{
    const int z = blockIdx.z;
    A   += (size_t)z * BB * NN * NN;
    Bp  += (size_t)z * bpStride;
    Out += (size_t)z * 2 * SZ66;

    const int t    = threadIdx.x;
    const int w    = t >> 5;
    const int lane = t & 31;
    const int g    = lane >> 2;
    const int tg   = lane & 3;
    const int b    = blockIdx.y;
    const int row0 = blockIdx.x * 64 + w * 16;

    const float* Ab = A + ((size_t)b * NN + row0) * NN;
    const uint4* Bb = Bp + (size_t)b * NJ * NKS * 32 + lane;

    float acc[NJ][4];
#pragma unroll
    for (int j = 0; j < NJ; j++)
#pragma unroll
        for (int q = 0; q < 4; q++) acc[j][q] = 0.0f;

    float2 ar[2][4];
    uint4  br[2][NJ];

    auto LD = [&](int ks, int p) {
        const int k = ks*16 + 2*tg;
        const float* ap = Ab + (size_t)g*NN + k;
        ar[p][0] = *(const float2*)(ap);
        ar[p][1] = *(const float2*)(ap + 8*NN);
        ar[p][2] = *(const float2*)(ap + 8);
        ar[p][3] = *(const float2*)(ap + 8*NN + 8);
#pragma unroll
        for (int j = 0; j < NJ; j++)
            br[p][j] = Bb[((size_t)j*NKS + ks)*32];
    };

    LD(0, 0);

    for (int ks = 0; ks < NKS; ks++) {
        const int p = ks & 1;
        if (ks < NKS-1) LD(ks+1, p ^ 1);

        uint32_t ah[4], al[4];
#pragma unroll
        for (int q = 0; q < 4; q++)
            split2(ar[p][q], ah[q], al[q]);

#pragma unroll
        for (int j = 0; j < NJ; j++) {
            uint32_t bh[2], bl[2];
            bh[0] = br[p][j].x; bh[1] = br[p][j].y;
            bl[0] = br[p][j].z; bl[1] = br[p][j].w;
            mma_bf16(acc[j], ah, bh);
            mma_bf16(acc[j], al, bh);
            mma_bf16(acc[j], ah, bl);
        }
    }

#pragma unroll
    for (int j = 0; j < NJ; j++) {
        int col = j*8 + 2*tg;
        if (col < DCAT) {
#pragma unroll
            for (int h2 = 0; h2 < 2; h2++) {
                int row = row0 + g + h2*8;
                size_t o = ((size_t)b * NN + row) * DCAT + col;
                float2 v;
                v.x = alpha * acc[j][h2*2 + 0];
                v.y = alpha * acc[j][h2*2 + 1];
                if (Base) {
                    float2 bs = *(const float2*)(Base + o);
                    v.x = fmaf(beta, bs.x, v.x);
                    v.y = fmaf(beta, bs.y, v.y);
                }
                *(float2*)(Out + o) = v;
            }
        }
    }
}

// ---------------------------------------------------------------------------
// Kernel 3: gate combine — 16 nodes/block, 384 thr; fused pack of candidate
// ---------------------------------------------------------------------------
__global__ __launch_bounds__(384) void combine_gate(
                             const float* __restrict__ X,
                             const float* __restrict__ T0,
                             const float* __restrict__ T1,
                             const float* __restrict__ T2,
                             const float* __restrict__ T3,
                             const float* __restrict__ gate_w,
                             const float* __restrict__ gate_b,
                             const float* __restrict__ xt,
                             const float* __restrict__ s1,
                             const float* __restrict__ s2,
                             float* __restrict__ cand,
                             float* __restrict__ r_out,
                             uint4* __restrict__ packC)
{
    __shared__ float s[16][DBASIS];
    __shared__ float cnd[16][68];
    const int t  = threadIdx.x;
    const int nb = blockIdx.x * 16;

    for (int idx = t; idx < 16*DBASIS; idx += 384) {
        int n = idx / DBASIS, i = idx - n*DBASIS;
        int term = i / DCAT, w = i - term*DCAT;
        const float* src;
        switch (term) {
            case 0: src = X;  break;
            case 1: src = T0; break;
            case 2: src = T1; break;
            case 3: src = X;  break;
            case 4: src = T2; break;
            default: src = T3; break;
        }
        s[n][i] = src[(size_t)(nb+n)*DCAT + w];
    }
    __syncthreads();

    const int c = t % 96;
    const int g = t / 96;
    float acc[4];
    float bc = gate_b[c];
#pragma unroll
    for (int q = 0; q < 4; q++) acc[q] = bc;

    for (int i = 0; i < DBASIS; i++) {
        float w = __ldg(&gate_w[i*GOUT + c]);
#pragma unroll
        for (int q = 0; q < 4; q++)
            acc[q] = fmaf(s[g*4 + q][i], w, acc[q]);
    }

#pragma unroll
    for (int q = 0; q < 4; q++) {
        int n = g*4 + q;
        int node = nb + n;
        float v = sigmoidf_(acc[q]);
        if (c < DO) {
            float cv = v * s1[node*DS + c];
            cand[(size_t)node*DCAT + DIN + c] = cv;
            cnd[n][DIN + c] = cv;
        } else if (c < 2*DO) {
            int cc = c - DO;
            float cv = v * s2[node*DS + cc];
            cand[(size_t)node*DCAT + DIN + DS + cc] = cv;
            cnd[n][DIN + DS + cc] = cv;
        } else {
            r_out[node*DO + (c - 2*DO)] = v;
        }
        if (c < DIN) {
            float cv = xt[node*DIN + c];
            cand[(size_t)node*DCAT + c] = cv;
            cnd[n][c] = cv;
        }
    }
    __syncthreads();

    if (t < 288) {
        const int bb = nb >> 11;
        const int kb = (nb & 2047) >> 4;
        pack_tile<68>(cnd, packC, bb, kb, t);
    }
}

// ---------------------------------------------------------------------------
// Kernel 4: final — 16 nodes/block, 512 thr
// ---------------------------------------------------------------------------
__global__ __launch_bounds__(512) void final_kernel(
                             const float* __restrict__ C,
                             const float* __restrict__ T0,
                             const float* __restrict__ T1,
                             const float* __restrict__ T2,
                             const float* __restrict__ T3,
                             const float* __restrict__ upd_w,
                             const float* __restrict__ upd_b,
                             const float* __restrict__ hop_w,
                             const float* __restrict__ hop_b,
                             const float* __restrict__ g_r,
                             const float* __restrict__ g_state,
                             float* __restrict__ out)
{
    __shared__ float s[16][DBASIS];
    __shared__ float hsh[16][DO];
    const int t  = threadIdx.x;
    const int nb = blockIdx.x * 16;

    for (int idx = t; idx < 16*DBASIS; idx += 512) {
        int n = idx / DBASIS, i = idx - n*DBASIS;
        int term = i / DCAT, w = i - term*DCAT;
        const float* src;
        switch (term) {
            case 0: src = C;  break;
            case 1: src = T0; break;
            case 2: src = T1; break;
            case 3: src = C;  break;
            case 4: src = T2; break;
            default: src = T3; break;
        }
        s[n][i] = src[(size_t)(nb+n)*DCAT + w];
    }
    __syncthreads();

    const int n = t >> 5;
    const int c = t & 31;
    const int node = nb + n;

    float acc = upd_b[c];
    for (int i = 0; i < DBASIS; i++)
        acc = fmaf(s[n][i], __ldg(&upd_w[i*DO + c]), acc);

    float hc = tanhf(acc);
    float r  = g_r[node*DO + c];
    float st = g_state[node*DS + c];
    float h  = r*st + (1.0f - r)*hc;

    out[(size_t)node*DO + c] = h;
    hsh[n][c] = h;
    __syncthreads();

    float a2 = hop_b[c];
#pragma unroll
    for (int i = 0; i < HID; i++)
        a2 = fmaf(hsh[n][i], hop_w[i*HID + c], a2);
    out[(size_t)TOTN*DO + (size_t)node*HID + c] = a2;
}

// ---------------------------------------------------------------------------
// launch
// ---------------------------------------------------------------------------
extern "C" void kernel_launch(void* const* d_in, const int* in_sizes, int n_in,
                              void* d_out, int out_size)
{
    const float* xt     = (const float*)d_in[0];
    const float* s1     = (const float*)d_in[1];
    const float* s2     = (const float*)d_in[2];
    const float* ge     = (const float*)d_in[3];
    const float* sup    = (const float*)d_in[4];
    const float* mlp_w  = (const float*)d_in[5];
    const float* mlp_b  = (const float*)d_in[6];
    const float* gate_w = (const float*)d_in[7];
    const float* gate_b = (const float*)d_in[8];
    const float* upd_w  = (const float*)d_in[9];
    const float* upd_b  = (const float*)d_in[10];
    const float* hop_w  = (const float*)d_in[11];
    const float* hop_b  = (const float*)d_in[12];
    float* out = (float*)d_out;

    float* scr = nullptr;
    cudaGetSymbolAddress((void**)&scr, g_scratch);
    uint4* pA = nullptr;
    cudaGetSymbolAddress((void**)&pA, g_packA);
    uint4* pB = nullptr;
    cudaGetSymbolAddress((void**)&pB, g_packB);

    float* gX  = scr + OFF_X;
    float* gC  = scr + OFF_C;
    float* gT0 = scr + OFF_T0;
    float* gT1 = scr + OFF_T1;
    float* gT2 = scr + OFF_T2;
    float* gT3 = scr + OFF_T3;
    float* gST = scr + OFF_ST;
    float* gR  = scr + OFF_R;

    dim3 ggrid(NN / 64, BB, 2);     // z = support
    dim3 pgrid(NKS, BB, 2);         // z = T0 / T2

    // 1. prep: mr/state + X + packed X
    prep_kernel<<<TOTN/16, 512>>>(xt, s1, s2, ge, mlp_w, mlp_b, gX, gST, pA);

    // 2. merged T0/T2, pack, merged T1/T3
    gemm_tc<<<ggrid, 128>>>(sup, pA, 0,          nullptr, gT0, 1.0f,  0.0f);
    pack_kernel<<<pgrid, 288>>>(gT0, 2*SZ66, pB);
    gemm_tc<<<ggrid, 128>>>(sup, pB, PACK_ELEMS, gX,      gT1, 2.0f, -1.0f);

    // 3. gate combine -> candidate (+packed), r
    combine_gate<<<TOTN/16, 384>>>(gX, gT0, gT1, gT2, gT3,
                                   gate_w, gate_b, xt, s1, s2, gC, gR, pA);

    // 4. merged T0/T2, pack, merged T1/T3 on candidate
    gemm_tc<<<ggrid, 128>>>(sup, pA, 0,          nullptr, gT0, 1.0f,  0.0f);
    pack_kernel<<<pgrid, 288>>>(gT0, 2*SZ66, pB);
    gemm_tc<<<ggrid, 128>>>(sup, pB, PACK_ELEMS, gC,      gT1, 2.0f, -1.0f);

    // 5. final
    final_kernel<<<TOTN/16, 512>>>(gC, gT0, gT1, gT2, gT3,
                                   upd_w, upd_b, hop_w, hop_b,
                                   gR, gST, out);
}

// round 12
// speedup vs baseline: 2.9739x; 2.0193x over previous
#include <cuda_runtime.h>
#include <cuda_bf16.h>
#include <cstdint>

// ---------------- problem constants ----------------
#define BB   8
#define NN   2048
#define DIN  2
#define DS   32
#define DO   32
#define GE   8
#define HID  32
#define DCAT 66
#define DGI  74
#define DBASIS 396
#define GOUT 96

#define TOTN (BB*NN)
#define SZ66 ((size_t)TOTN*DCAT)
#define SZ32 ((size_t)TOTN*DO)

#define NJ 9                 // n8 blocks (72 cols, 66 used)
#define NKS 128              // k16 blocks
#define PACK_ELEMS ((size_t)BB*NJ*NKS*32)   // uint4 per pack image

__device__ float g_scratch[6*1081344 + 2*524288];
__device__ uint4 g_packA[PACK_ELEMS];       // packed X or C
__device__ uint4 g_packB[2*PACK_ELEMS];     // packed T0 (slot0) / T2 (slot1)

#define OFF_X  ((size_t)0)
#define OFF_C  (SZ66)
#define OFF_T0 (2*SZ66)
#define OFF_T1 (3*SZ66)
#define OFF_T2 (4*SZ66)
#define OFF_T3 (5*SZ66)
#define OFF_ST (6*SZ66)
#define OFF_R  (6*SZ66 + SZ32)

__device__ __forceinline__ float sigmoidf_(float x) {
    return 1.0f / (1.0f + __expf(-x));
}

__device__ __forceinline__ void mma_bf16(float c[4], const uint32_t a[4], const uint32_t b[2]) {
    asm volatile(
        "mma.sync.aligned.m16n8k16.row.col.f32.bf16.bf16.f32 "
        "{%0,%1,%2,%3},{%4,%5,%6,%7},{%8,%9},{%0,%1,%2,%3};"
        : "+f"(c[0]), "+f"(c[1]), "+f"(c[2]), "+f"(c[3])
        : "r"(a[0]), "r"(a[1]), "r"(a[2]), "r"(a[3]), "r"(b[0]), "r"(b[1]));
}

__device__ __forceinline__ void cp_async16(void* smem, const void* gmem) {
    uint32_t s = (uint32_t)__cvta_generic_to_shared(smem);
    asm volatile("cp.async.cg.shared.global [%0], [%1], 16;\n" :: "r"(s), "l"(gmem));
}
__device__ __forceinline__ void cp_commit() {
    asm volatile("cp.async.commit_group;\n" ::: "memory");
}
template<int N>
__device__ __forceinline__ void cp_wait() {
    asm volatile("cp.async.wait_group %0;\n" :: "n"(N) : "memory");
}

// split float2 -> bf16x2 high + bf16x2 low-residual
__device__ __forceinline__ void split2(float2 v, uint32_t& h, uint32_t& l) {
    __nv_bfloat162 hh = __float22bfloat162_rn(v);
    h = *(uint32_t*)&hh;
    float2 r;
    r.x = v.x - __low2float(hh);
    r.y = v.y - __high2float(hh);
    __nv_bfloat162 ll = __float22bfloat162_rn(r);
    l = *(uint32_t*)&ll;
}

// pack one 16-node x 66-col tile (smem) -> fragment-native h/l image.
template<int TS>
__device__ __forceinline__ void pack_tile(const float (*tile)[TS], uint4* dst,
                                          int b, int kb, int t)
{
    const int j    = t >> 5;
    const int lane = t & 31;
    const int g    = lane >> 2;
    const int tg   = lane & 3;
    const int n    = j*8 + g;

    float v0 = 0.f, v1 = 0.f, v2 = 0.f, v3 = 0.f;
    if (n < DCAT) {
        v0 = tile[2*tg    ][n];
        v1 = tile[2*tg + 1][n];
        v2 = tile[2*tg + 8][n];
        v3 = tile[2*tg + 9][n];
    }
    uint32_t h01, l01, h89, l89;
    split2(make_float2(v0, v1), h01, l01);
    split2(make_float2(v2, v3), h89, l89);

    uint4 o; o.x = h01; o.y = h89; o.z = l01; o.w = l89;
    dst[((size_t)(b*NJ + j)*NKS + kb)*32 + lane] = o;
}

// ---------------------------------------------------------------------------
// Kernel 1: prep — gate MLP -> mr -> state; write X and packed X
// ---------------------------------------------------------------------------
__global__ __launch_bounds__(512) void prep_kernel(
                            const float* __restrict__ xt,
                            const float* __restrict__ s1,
                            const float* __restrict__ s2,
                            const float* __restrict__ ge,
                            const float* __restrict__ mlp_w,
                            const float* __restrict__ mlp_b,
                            float* __restrict__ gX,
                            float* __restrict__ gstate,
                            uint4* __restrict__ packX)
{
    __shared__ float sg[16][DGI];
    const int t  = threadIdx.x;
    const int nb = blockIdx.x * 16;

    for (int idx = t; idx < 16 * DGI; idx += 512) {
        int nn = idx / DGI, i = idx % DGI;
        int node = nb + nn;
        float v;
        if (i < DIN)            v = xt[node*DIN + i];
        else if (i < DIN+DS)    v = s1[node*DS + (i-DIN)];
        else if (i < DIN+2*DS)  v = s2[node*DS + (i-DIN-DS)];
        else                    v = ge[node*GE + (i-DIN-2*DS)];
        sg[nn][i] = v;
    }
    __syncthreads();

    for (int idx = t; idx < 16 * DCAT; idx += 512) {
        int nn = idx / DCAT, i = idx % DCAT;
        gX[(size_t)(nb+nn)*DCAT + i] = sg[nn][i];
    }

    const int n = t >> 5;
    const int c = t & 31;
    float acc = mlp_b[c];
#pragma unroll 8
    for (int i = 0; i < DGI; i++)
        acc = fmaf(sg[n][i], mlp_w[i*DO + c], acc);
    float mr = sigmoidf_(acc);

    int node = nb + n;
    float a = s1[node*DS + c];
    float b = s2[node*DS + c];
    gstate[node*DS + c] = mr*a + (1.0f - mr)*b;

    if (t < 288) {
        const int bb = nb >> 11;
        const int kb = (nb & 2047) >> 4;
        pack_tile<DGI>(sg, packX, bb, kb, t);
    }
}

// ---------------------------------------------------------------------------
// Pack kernel (T0/T2): grid (128, 8, 2)
// ---------------------------------------------------------------------------
__global__ __launch_bounds__(288) void pack_kernel(const float* __restrict__ src,
                                                   size_t srcStride,
                                                   uint4* __restrict__ dst)
{
    __shared__ float tile[16][68];
    const int t  = threadIdx.x;
    const int kb = blockIdx.x;
    const int b  = blockIdx.y;
    const int z  = blockIdx.z;
    src += (size_t)z * srcStride;
    dst += (size_t)z * PACK_ELEMS;
    const int node0 = b*NN + kb*16;

    for (int idx = t; idx < 16*DCAT; idx += 288) {
        int r = idx / DCAT, c = idx - r*DCAT;
        tile[r][c] = src[(size_t)(node0 + r)*DCAT + c];
    }
    __syncthreads();
    pack_tile<68>(tile, dst, b, kb, t);
}

// ---------------------------------------------------------------------------
// Kernel 2: hybrid tensor-core GEMM, merged supports (blockIdx.z)
// A: direct-LDG fp32 fragments, in-reg bf16 split (3-product)
// B: packed frag image staged via cp.async into 4-stage smem ring, LDS.128
// CTA: 128 thr = 4 warps x m16 (M-tile 64); grid (32, 8, 2)
// ---------------------------------------------------------------------------
#define STAGES 4
__global__ __launch_bounds__(128) void gemm_tc(const float* __restrict__ A,
                                               const uint4* __restrict__ Bp,
                                               size_t bpStride,
                                               const float* __restrict__ Base,
                                               float* __restrict__ Out,
                                               float alpha, float beta)
{
    __shared__ uint4 sB[STAGES][NJ*32];     // 4 x 4608 B

    const int z = blockIdx.z;
    A   += (size_t)z * BB * NN * NN;
    Bp  += (size_t)z * bpStride;
    Out += (size_t)z * 2 * SZ66;

    const int t    = threadIdx.x;
    const int w    = t >> 5;
    const int lane = t & 31;
    const int g    = lane >> 2;
    const int tg   = lane & 3;
    const int b    = blockIdx.y;
    const int row0 = blockIdx.x * 64 + w * 16;

    const float* Ab = A + ((size_t)b * NN + row0) * NN;
    const uint4* Bb = Bp + (size_t)b * NJ * NKS * 32;

    float acc[NJ][4];
#pragma unroll
    for (int j = 0; j < NJ; j++)
#pragma unroll
        for (int q = 0; q < 4; q++) acc[j][q] = 0.0f;

    float2 ar[2][4];

    auto ISSUE_B = [&](int ks) {
        const int slot = ks & (STAGES-1);
        // 288 uint4; threads 0..127 take idx t, t+128, t+256
        cp_async16(&sB[slot][t],       Bb + ((size_t)(t >> 5)*NKS + ks)*32 + (t & 31));
        {
            int idx = t + 128;
            cp_async16(&sB[slot][idx], Bb + ((size_t)(idx >> 5)*NKS + ks)*32 + (idx & 31));
        }
        if (t < 32) {
            int idx = t + 256;
            cp_async16(&sB[slot][idx], Bb + ((size_t)(idx >> 5)*NKS + ks)*32 + (idx & 31));
        }
    };
    auto LD_A = [&](int ks, int p) {
        const int k = ks*16 + 2*tg;
        const float* ap = Ab + (size_t)g*NN + k;
        ar[p][0] = *(const float2*)(ap);
        ar[p][1] = *(const float2*)(ap + 8*NN);
        ar[p][2] = *(const float2*)(ap + 8);
        ar[p][3] = *(const float2*)(ap + 8*NN + 8);
    };

    // prologue: two B stages in flight, A stage 0 in regs
    ISSUE_B(0); cp_commit();
    ISSUE_B(1); cp_commit();
    LD_A(0, 0);

    for (int ks = 0; ks < NKS; ks++) {
        const int p = ks & 1;
        // keep 2 stages ahead
        if (ks + 2 < NKS) ISSUE_B(ks + 2);
        cp_commit();                        // always commit (uniform group count)
        if (ks + 1 < NKS) LD_A(ks + 1, p ^ 1);

        cp_wait<2>();                       // stage ks landed
        __syncthreads();

        uint32_t ah[4], al[4];
#pragma unroll
        for (int q = 0; q < 4; q++)
            split2(ar[p][q], ah[q], al[q]);

        const uint4* bs = &sB[ks & (STAGES-1)][lane];
#pragma unroll
        for (int j = 0; j < NJ; j++) {
            uint4 bj = bs[j*32];
            uint32_t bh[2], bl[2];
            bh[0] = bj.x; bh[1] = bj.y;
            bl[0] = bj.z; bl[1] = bj.w;
            mma_bf16(acc[j], ah, bh);
            mma_bf16(acc[j], al, bh);
            mma_bf16(acc[j], ah, bl);
        }
    }

#pragma unroll
    for (int j = 0; j < NJ; j++) {
        int col = j*8 + 2*tg;
        if (col < DCAT) {
#pragma unroll
            for (int h2 = 0; h2 < 2; h2++) {
                int row = row0 + g + h2*8;
                size_t o = ((size_t)b * NN + row) * DCAT + col;
                float2 v;
                v.x = alpha * acc[j][h2*2 + 0];
                v.y = alpha * acc[j][h2*2 + 1];
                if (Base) {
                    float2 bs2 = *(const float2*)(Base + o);
                    v.x = fmaf(beta, bs2.x, v.x);
                    v.y = fmaf(beta, bs2.y, v.y);
                }
                *(float2*)(Out + o) = v;
            }
        }
    }
}

// ---------------------------------------------------------------------------
// Kernel 3: gate combine — fused pack of candidate
// ---------------------------------------------------------------------------
__global__ __launch_bounds__(384) void combine_gate(
                             const float* __restrict__ X,
                             const float* __restrict__ T0,
                             const float* __restrict__ T1,
                             const float* __restrict__ T2,
                             const float* __restrict__ T3,
                             const float* __restrict__ gate_w,
                             const float* __restrict__ gate_b,
                             const float* __restrict__ xt,
                             const float* __restrict__ s1,
                             const float* __restrict__ s2,
                             float* __restrict__ cand,
                             float* __restrict__ r_out,
                             uint4* __restrict__ packC)
{
    __shared__ float s[16][DBASIS];
    __shared__ float cnd[16][68];
    const int t  = threadIdx.x;
    const int nb = blockIdx.x * 16;

    for (int idx = t; idx < 16*DBASIS; idx += 384) {
        int n = idx / DBASIS, i = idx - n*DBASIS;
        int term = i / DCAT, w = i - term*DCAT;
        const float* src;
        switch (term) {
            case 0: src = X;  break;
            case 1: src = T0; break;
            case 2: src = T1; break;
            case 3: src = X;  break;
            case 4: src = T2; break;
            default: src = T3; break;
        }
        s[n][i] = src[(size_t)(nb+n)*DCAT + w];
    }
    __syncthreads();

    const int c = t % 96;
    const int g = t / 96;
    float acc[4];
    float bc = gate_b[c];
#pragma unroll
    for (int q = 0; q < 4; q++) acc[q] = bc;

    for (int i = 0; i < DBASIS; i++) {
        float w = __ldg(&gate_w[i*GOUT + c]);
#pragma unroll
        for (int q = 0; q < 4; q++)
            acc[q] = fmaf(s[g*4 + q][i], w, acc[q]);
    }

#pragma unroll
    for (int q = 0; q < 4; q++) {
        int n = g*4 + q;
        int node = nb + n;
        float v = sigmoidf_(acc[q]);
        if (c < DO) {
            float cv = v * s1[node*DS + c];
            cand[(size_t)node*DCAT + DIN + c] = cv;
            cnd[n][DIN + c] = cv;
        } else if (c < 2*DO) {
            int cc = c - DO;
            float cv = v * s2[node*DS + cc];
            cand[(size_t)node*DCAT + DIN + DS + cc] = cv;
            cnd[n][DIN + DS + cc] = cv;
        } else {
            r_out[node*DO + (c - 2*DO)] = v;
        }
        if (c < DIN) {
            float cv = xt[node*DIN + c];
            cand[(size_t)node*DCAT + c] = cv;
            cnd[n][c] = cv;
        }
    }
    __syncthreads();

    if (t < 288) {
        const int bb = nb >> 11;
        const int kb = (nb & 2047) >> 4;
        pack_tile<68>(cnd, packC, bb, kb, t);
    }
}

// ---------------------------------------------------------------------------
// Kernel 4: final
// ---------------------------------------------------------------------------
__global__ __launch_bounds__(512) void final_kernel(
                             const float* __restrict__ C,
                             const float* __restrict__ T0,
                             const float* __restrict__ T1,
                             const float* __restrict__ T2,
                             const float* __restrict__ T3,
                             const float* __restrict__ upd_w,
                             const float* __restrict__ upd_b,
                             const float* __restrict__ hop_w,
                             const float* __restrict__ hop_b,
                             const float* __restrict__ g_r,
                             const float* __restrict__ g_state,
                             float* __restrict__ out)
{
    __shared__ float s[16][DBASIS];
    __shared__ float hsh[16][DO];
    const int t  = threadIdx.x;
    const int nb = blockIdx.x * 16;

    for (int idx = t; idx < 16*DBASIS; idx += 512) {
        int n = idx / DBASIS, i = idx - n*DBASIS;
        int term = i / DCAT, w = i - term*DCAT;
        const float* src;
        switch (term) {
            case 0: src = C;  break;
            case 1: src = T0; break;
            case 2: src = T1; break;
            case 3: src = C;  break;
            case 4: src = T2; break;
            default: src = T3; break;
        }
        s[n][i] = src[(size_t)(nb+n)*DCAT + w];
    }
    __syncthreads();

    const int n = t >> 5;
    const int c = t & 31;
    const int node = nb + n;

    float acc = upd_b[c];
    for (int i = 0; i < DBASIS; i++)
        acc = fmaf(s[n][i], __ldg(&upd_w[i*DO + c]), acc);

    float hc = tanhf(acc);
    float r  = g_r[node*DO + c];
    float st = g_state[node*DS + c];
    float h  = r*st + (1.0f - r)*hc;

    out[(size_t)node*DO + c] = h;
    hsh[n][c] = h;
    __syncthreads();

    float a2 = hop_b[c];
#pragma unroll
    for (int i = 0; i < HID; i++)
        a2 = fmaf(hsh[n][i], hop_w[i*HID + c], a2);
    out[(size_t)TOTN*DO + (size_t)node*HID + c] = a2;
}

// ---------------------------------------------------------------------------
// launch
// ---------------------------------------------------------------------------
extern "C" void kernel_launch(void* const* d_in, const int* in_sizes, int n_in,
                              void* d_out, int out_size)
{
    const float* xt     = (const float*)d_in[0];
    const float* s1     = (const float*)d_in[1];
    const float* s2     = (const float*)d_in[2];
    const float* ge     = (const float*)d_in[3];
    const float* sup    = (const float*)d_in[4];
    const float* mlp_w  = (const float*)d_in[5];
    const float* mlp_b  = (const float*)d_in[6];
    const float* gate_w = (const float*)d_in[7];
    const float* gate_b = (const float*)d_in[8];
    const float* upd_w  = (const float*)d_in[9];
    const float* upd_b  = (const float*)d_in[10];
    const float* hop_w  = (const float*)d_in[11];
    const float* hop_b  = (const float*)d_in[12];
    float* out = (float*)d_out;

    float* scr = nullptr;
    cudaGetSymbolAddress((void**)&scr, g_scratch);
    uint4* pA = nullptr;
    cudaGetSymbolAddress((void**)&pA, g_packA);
    uint4* pB = nullptr;
    cudaGetSymbolAddress((void**)&pB, g_packB);

    float* gX  = scr + OFF_X;
    float* gC  = scr + OFF_C;
    float* gT0 = scr + OFF_T0;
    float* gT1 = scr + OFF_T1;
    float* gT2 = scr + OFF_T2;
    float* gT3 = scr + OFF_T3;
    float* gST = scr + OFF_ST;
    float* gR  = scr + OFF_R;

    dim3 ggrid(NN / 64, BB, 2);     // z = support
    dim3 pgrid(NKS, BB, 2);         // z = T0 / T2

    prep_kernel<<<TOTN/16, 512>>>(xt, s1, s2, ge, mlp_w, mlp_b, gX, gST, pA);

    gemm_tc<<<ggrid, 128>>>(sup, pA, 0,          nullptr, gT0, 1.0f,  0.0f);
    pack_kernel<<<pgrid, 288>>>(gT0, 2*SZ66, pB);
    gemm_tc<<<ggrid, 128>>>(sup, pB, PACK_ELEMS, gX,      gT1, 2.0f, -1.0f);

    combine_gate<<<TOTN/16, 384>>>(gX, gT0, gT1, gT2, gT3,
                                   gate_w, gate_b, xt, s1, s2, gC, gR, pA);

    gemm_tc<<<ggrid, 128>>>(sup, pA, 0,          nullptr, gT0, 1.0f,  0.0f);
    pack_kernel<<<pgrid, 288>>>(gT0, 2*SZ66, pB);
    gemm_tc<<<ggrid, 128>>>(sup, pB, PACK_ELEMS, gC,      gT1, 2.0f, -1.0f);

    final_kernel<<<TOTN/16, 512>>>(gC, gT0, gT1, gT2, gT3,
                                   upd_w, upd_b, hop_w, hop_b,
                                   gR, gST, out);
}